// round 13
// baseline (speedup 1.0000x reference)
#include <cuda_runtime.h>
#include <cuda_bf16.h>
#include <cstdint>

// ---------------------------------------------------------------------------
// Problem constants
// ---------------------------------------------------------------------------
static constexpr int Bb = 16;
static constexpr int Cc = 1024;
static constexpr int Tt = 2048;
static constexpr int Kk = 4096;
static constexpr int Nrows = Bb * Tt;  // 32768

static constexpr float MARGIN = 2.0f;   // bf16-calibrated (proven exact R3/R7/R10-12)
static constexpr int   NCAND  = 128;    // E[count]~40-60 with 8 K-slices; P(>128)~0

// Main GEMM: persistent CTAs, work item = (rowblock, K-eighth).
static constexpr int TM = 128;
static constexpr int TN = 128;
static constexpr int KSLICE = 512;                // cols per item (4 k-tiles)
static constexpr int NITEMS = (Nrows / TM) * (Kk / KSLICE);   // 2048
static constexpr int NKT_I = KSLICE / TN;         // 4 k-tiles per item
static constexpr int NSTG = NKT_I * 16;           // 64 stages per item

static constexpr int A_STAGE = TM * 128;          // 16KB (128B rows, 64 bf16)
static constexpr int STAGE_BYTES = 2 * A_STAGE;   // 32KB
static constexpr uint32_t SMEM_TOTAL = 3 * STAGE_BYTES;   // 96KB

static constexpr int GRID_MAIN = 296;             // 2 CTAs/SM x 148 SMs

// ---------------------------------------------------------------------------
// Device scratch (no cudaMalloc allowed)
// ---------------------------------------------------------------------------
__device__ __align__(1024) __nv_bfloat16 g_xb[(size_t)Nrows * Cc];  // transposed bf16 x
__device__ __align__(1024) float         g_xf[(size_t)Nrows * Cc];  // transposed fp32 x
__device__ __align__(1024) __nv_bfloat16 g_cb[(size_t)Kk * Cc];     // bf16 centroids
__device__ float g_csq[Kk];
__device__ unsigned long long g_cand[Nrows][NCAND];
__device__ int g_ccount[Nrows];
__device__ int g_amin[Nrows];
__device__ int g_wctr;                            // work-queue counter

// ---------------------------------------------------------------------------
// Helpers
// ---------------------------------------------------------------------------
__device__ __forceinline__ uint32_t smem_u32(const void* p) {
    uint32_t a;
    asm("{ .reg .u64 t; cvta.to.shared.u64 t, %1; cvt.u32.u64 %0, t; }" : "=r"(a) : "l"(p));
    return a;
}
__device__ __forceinline__ unsigned enc(float f) {
    unsigned u = __float_as_uint(f);
    return u ^ ((unsigned)((int)u >> 31) | 0x80000000u);
}
__device__ __forceinline__ float dec(unsigned u) {
    unsigned m = ((int)u >= 0) ? 0xFFFFFFFFu : 0x80000000u;
    return __uint_as_float(u ^ m);
}

#define CP16(sm, gp) \
    asm volatile("cp.async.cg.shared.global [%0], [%1], 16;" :: "r"(sm), "l"(gp))
#define CP_COMMIT() asm volatile("cp.async.commit_group;" ::: "memory")
#define CP_WAIT1()  asm volatile("cp.async.wait_group 1;" ::: "memory")

#define LDSM4(f, a) \
    asm volatile("ldmatrix.sync.aligned.m8n8.x4.shared.b16 {%0,%1,%2,%3}, [%4];" \
        : "=r"((f)[0]), "=r"((f)[1]), "=r"((f)[2]), "=r"((f)[3]) : "r"(a))

#define MMA16816(c, a, b0v, b1v)                                               \
    asm volatile("mma.sync.aligned.m16n8k16.row.col.f32.bf16.bf16.f32 "        \
        "{%0,%1,%2,%3},{%4,%5,%6,%7},{%8,%9},{%0,%1,%2,%3};"                   \
        : "+f"((c)[0]), "+f"((c)[1]), "+f"((c)[2]), "+f"((c)[3])               \
        : "r"((a)[0]), "r"((a)[1]), "r"((a)[2]), "r"((a)[3]),                  \
          "r"(b0v), "r"(b1v))

// ---------------------------------------------------------------------------
// Kernel 0: zero counters + work queue (graph replays need re-zero per launch)
// ---------------------------------------------------------------------------
__global__ void init_kernel() {
    g_ccount[blockIdx.x * 256 + threadIdx.x] = 0;
    if (blockIdx.x == 0 && threadIdx.x == 0) g_wctr = 0;
}

// ---------------------------------------------------------------------------
// Kernel 1: transpose + convert feature -> g_xf (fp32), g_xb (bf16)
// ---------------------------------------------------------------------------
__global__ void convert_kernel(const float* __restrict__ feat) {
    __shared__ float tile[32][33];
    const int t0 = blockIdx.x * 32, c0 = blockIdx.y * 32, b = blockIdx.z;
    const int tx = threadIdx.x, ty = threadIdx.y;
    #pragma unroll
    for (int cc = ty; cc < 32; cc += 8)
        tile[cc][tx] = feat[(size_t)b * Cc * Tt + (size_t)(c0 + cc) * Tt + t0 + tx];
    __syncthreads();
    #pragma unroll
    for (int tt = ty; tt < 32; tt += 8) {
        float v = tile[tx][tt];
        size_t off = (size_t)(b * Tt + t0 + tt) * Cc + c0 + tx;
        g_xf[off] = v;
        g_xb[off] = __float2bfloat16(v);
    }
}

// ---------------------------------------------------------------------------
// Kernel 2: csq (fp64 accum) + bf16 centroid conversion
// ---------------------------------------------------------------------------
__global__ void csq_kernel(const float* __restrict__ cent) {
    int k = blockIdx.x * 8 + (threadIdx.x >> 5);
    int lane = threadIdx.x & 31;
    const float* row = cent + (size_t)k * Cc;
    double s = 0.0;
    #pragma unroll
    for (int i = 0; i < Cc / 128; i++) {
        float4 v = *reinterpret_cast<const float4*>(row + i * 128 + lane * 4);
        s += (double)v.x * v.x + (double)v.y * v.y + (double)v.z * v.z + (double)v.w * v.w;
        __nv_bfloat162 p0 = __floats2bfloat162_rn(v.x, v.y);
        __nv_bfloat162 p1 = __floats2bfloat162_rn(v.z, v.w);
        *reinterpret_cast<__nv_bfloat162*>(&g_cb[(size_t)k * Cc + i * 128 + lane * 4]) = p0;
        *reinterpret_cast<__nv_bfloat162*>(&g_cb[(size_t)k * Cc + i * 128 + lane * 4 + 2]) = p1;
    }
    #pragma unroll
    for (int off = 16; off; off >>= 1) s += __shfl_down_sync(0xffffffffu, s, off);
    if (lane == 0) g_csq[k] = (float)s;
}

// ---------------------------------------------------------------------------
// Kernel 3: persistent HMMA GEMM + single-pass shortlist epilogue.
// Work item = (rowblock, K-eighth). 8 warps 2x4, warp tile 64x32,
// 64-deep stages, 3-buffer cp.async pipeline (restart per item).
// ---------------------------------------------------------------------------
__global__ __launch_bounds__(256, 2)
void argmin_hmma_kernel() {
    extern __shared__ char smem[];
    const uint32_t sb = smem_u32(smem);
    __shared__ int s_w;

    const int tid  = threadIdx.x;
    const int lane = tid & 31;
    const int wid  = tid >> 5;
    const int wm0  = (wid & 1) * 64;
    const int wn0  = (wid >> 1) * 32;

    const int arow  = lane & 15, ahalf = lane >> 4;
    const int browl = (lane & 7) + ((lane >> 4) << 3);
    const int bhalf = (lane >> 3) & 1;

    while (true) {
        __syncthreads();
        if (tid == 0) s_w = atomicAdd(&g_wctr, 1);
        __syncthreads();
        const int w = s_w;
        if (w >= NITEMS) break;

        const int rowbase = (w & 255) * TM;       // rb fast-varying: B reuse in L2
        const int kbase   = (w >> 8) * KSLICE;

        const char* Ag0 = (const char*)g_xb + (size_t)rowbase * 2048;
        const char* Bg0 = (const char*)g_cb + (size_t)kbase * 2048;

        auto load_stage = [&](int s, int bf) {
            if (s < NSTG) {
                const int kt = s >> 4, cc = s & 15;
                const uint32_t st = sb + bf * STAGE_BYTES;
                const char* ag = Ag0 + cc * 128;
                const char* bg = Bg0 + (size_t)(kt * TN) * 2048 + cc * 128;
                #pragma unroll
                for (int j = 0; j < 4; j++) {
                    const int ch = tid + j * 256;
                    const int r = ch >> 3, c = ch & 7;
                    CP16(st + r * 128 + ((c ^ (r & 7)) << 4), ag + (size_t)r * 2048 + c * 16);
                }
                const uint32_t bst = st + A_STAGE;
                #pragma unroll
                for (int j = 0; j < 4; j++) {
                    const int ch = tid + j * 256;
                    const int r = ch >> 3, c = ch & 7;
                    CP16(bst + r * 128 + ((c ^ (r & 7)) << 4), bg + (size_t)r * 2048 + c * 16);
                }
            }
            CP_COMMIT();
        };

        load_stage(0, 0); load_stage(1, 1);
        int buf = 0, nbuf = 2;

        // per-quad running min for this item's K-slice
        float runmin[4][2];
        #pragma unroll
        for (int mi = 0; mi < 4; mi++) { runmin[mi][0] = 3.0e38f; runmin[mi][1] = 3.0e38f; }

        for (int kt = 0; kt < NKT_I; ++kt) {
            float acc[4][4][4];
            #pragma unroll
            for (int mi = 0; mi < 4; mi++)
                #pragma unroll
                for (int ni = 0; ni < 4; ni++)
                    #pragma unroll
                    for (int q = 0; q < 4; q++) acc[mi][ni][q] = 0.0f;

            for (int cc = 0; cc < 16; ++cc) {
                const int s = (kt << 4) + cc;
                CP_WAIT1();
                __syncthreads();
                load_stage(s + 2, nbuf);
                const uint32_t st = sb + buf * STAGE_BYTES;
                buf = (buf + 1 == 3) ? 0 : buf + 1;
                nbuf = (nbuf + 1 == 3) ? 0 : nbuf + 1;

                #pragma unroll
                for (int ks = 0; ks < 4; ++ks) {
                    uint32_t af[4][4];
                    #pragma unroll
                    for (int mi = 0; mi < 4; mi++) {
                        const int r = wm0 + mi * 16 + arow;
                        LDSM4(af[mi], st + r * 128 + ((((ks << 1) + ahalf) ^ (r & 7)) << 4));
                    }
                    uint32_t bfr[2][4];
                    #pragma unroll
                    for (int p = 0; p < 2; p++) {
                        const int r = wn0 + p * 16 + browl;
                        LDSM4(bfr[p], st + A_STAGE + r * 128 +
                                      ((((ks << 1) + bhalf) ^ (r & 7)) << 4));
                    }
                    #pragma unroll
                    for (int mi = 0; mi < 4; mi++)
                        #pragma unroll
                        for (int ni = 0; ni < 4; ni++)
                            MMA16816(acc[mi][ni], af[mi],
                                     bfr[ni >> 1][(ni & 1) * 2],
                                     bfr[ni >> 1][(ni & 1) * 2 + 1]);
                }
            }

            // ---- single-pass epilogue: quad running min + direct append ----
            float csqv[8];
            #pragma unroll
            for (int ni = 0; ni < 4; ni++)
                #pragma unroll
                for (int c = 0; c < 2; c++)
                    csqv[ni * 2 + c] =
                        g_csq[kbase + kt * TN + wn0 + ni * 8 + (lane & 3) * 2 + c];

            #pragma unroll
            for (int mi = 0; mi < 4; mi++)
                #pragma unroll
                for (int rh = 0; rh < 2; rh++) {
                    float d[8];
                    float dmin = 3.0e38f;
                    #pragma unroll
                    for (int j = 0; j < 8; j++) {
                        d[j] = fmaf(acc[mi][j >> 1][rh * 2 + (j & 1)], -2.0f, csqv[j]);
                        dmin = fminf(dmin, d[j]);
                    }
                    dmin = fminf(dmin, __shfl_xor_sync(0xffffffffu, dmin, 1));
                    dmin = fminf(dmin, __shfl_xor_sync(0xffffffffu, dmin, 2));
                    const float thr = fminf(runmin[mi][rh], dmin) + MARGIN;
                    runmin[mi][rh] = fminf(runmin[mi][rh], dmin);
                    const int row = rowbase + wm0 + mi * 16 + (lane >> 2) + rh * 8;
                    #pragma unroll
                    for (int j = 0; j < 8; j++) {
                        if (d[j] < thr) {
                            const int kcol = kbase + kt * TN + wn0 +
                                             (j >> 1) * 8 + (lane & 3) * 2 + (j & 1);
                            const int idx = atomicAdd(&g_ccount[row], 1);
                            if (idx < NCAND)
                                g_cand[row][idx] =
                                    ((unsigned long long)enc(d[j]) << 32) | (unsigned)kcol;
                        }
                    }
                }
        }
    }
}

// ---------------------------------------------------------------------------
// Kernel 4: exact fp32 re-rank (one warp per row); >NCAND candidates -> scan
// ---------------------------------------------------------------------------
__global__ __launch_bounds__(256)
void rerank_kernel(const float* __restrict__ cent) {
    const int lane = threadIdx.x & 31;
    const int row = blockIdx.x * 8 + (threadIdx.x >> 5);
    const int n = g_ccount[row];

    float4 xv[8];
    const float4* xr = reinterpret_cast<const float4*>(g_xf + (size_t)row * Cc);
    #pragma unroll
    for (int i = 0; i < 8; i++) xv[i] = xr[i * 32 + lane];

    unsigned long long best = ~0ULL;
    if (n <= NCAND) {
        unsigned long long mn = ~0ULL;
        #pragma unroll
        for (int h = 0; h < 4; h++) {
            const int i = lane + h * 32;
            if (i < n) {
                unsigned long long v = g_cand[row][i];
                mn = (v < mn) ? v : mn;
            }
        }
        #pragma unroll
        for (int off = 16; off; off >>= 1) {
            unsigned long long o = __shfl_xor_sync(0xffffffffu, mn, off);
            mn = (o < mn) ? o : mn;
        }
        const unsigned thrk = enc(dec((unsigned)(mn >> 32)) + MARGIN);
        for (int i = 0; i < n; i++) {
            const unsigned long long ki = g_cand[row][i];   // broadcast load
            if ((unsigned)(ki >> 32) >= thrk) continue;
            const int k = (int)(ki & 0xffffffffu);
            const float4* crp = reinterpret_cast<const float4*>(cent + (size_t)k * Cc);
            float s = 0.f;
            #pragma unroll
            for (int i2 = 0; i2 < 8; i2++) {
                float4 cv = crp[i2 * 32 + lane];
                s = fmaf(xv[i2].x, cv.x, s); s = fmaf(xv[i2].y, cv.y, s);
                s = fmaf(xv[i2].z, cv.z, s); s = fmaf(xv[i2].w, cv.w, s);
            }
            #pragma unroll
            for (int off = 16; off; off >>= 1) s += __shfl_xor_sync(0xffffffffu, s, off);
            const float dd = fmaf(s, -2.0f, g_csq[k]);
            unsigned long long key = ((unsigned long long)enc(dd) << 32) | (unsigned)k;
            best = (key < best) ? key : best;
        }
    } else {
        for (int k = 0; k < Kk; k++) {
            const float4* crp = reinterpret_cast<const float4*>(cent + (size_t)k * Cc);
            float s = 0.f;
            #pragma unroll
            for (int i2 = 0; i2 < 8; i2++) {
                float4 cv = crp[i2 * 32 + lane];
                s = fmaf(xv[i2].x, cv.x, s); s = fmaf(xv[i2].y, cv.y, s);
                s = fmaf(xv[i2].z, cv.z, s); s = fmaf(xv[i2].w, cv.w, s);
            }
            #pragma unroll
            for (int off = 16; off; off >>= 1) s += __shfl_xor_sync(0xffffffffu, s, off);
            const float dd = fmaf(s, -2.0f, g_csq[k]);
            unsigned long long key = ((unsigned long long)enc(dd) << 32) | (unsigned)k;
            best = (key < best) ? key : best;
        }
    }
    if (lane == 0) g_amin[row] = (int)(best & 0xffffffffu);
}

// ---------------------------------------------------------------------------
// Kernel 5: output = feature - centroid[amin]
// ---------------------------------------------------------------------------
__global__ void output_kernel(const float* __restrict__ feat,
                              const float* __restrict__ cent,
                              float* __restrict__ out) {
    __shared__ float ctile[32][33];
    const int t0 = blockIdx.x * 32, c0 = blockIdx.y * 32, b = blockIdx.z;
    const int tx = threadIdx.x, ty = threadIdx.y;
    #pragma unroll
    for (int tt = ty; tt < 32; tt += 8) {
        int kidx = g_amin[b * Tt + t0 + tt];
        ctile[tt][tx] = cent[(size_t)kidx * Cc + c0 + tx];
    }
    __syncthreads();
    #pragma unroll
    for (int cc = ty; cc < 32; cc += 8) {
        size_t off = (size_t)b * Cc * Tt + (size_t)(c0 + cc) * Tt + t0 + tx;
        out[off] = feat[off] - ctile[tx][cc];
    }
}

// ---------------------------------------------------------------------------
extern "C" void kernel_launch(void* const* d_in, const int* in_sizes, int n_in,
                              void* d_out, int out_size) {
    const float* feat = (const float*)d_in[0];
    const float* cent = (const float*)d_in[1];
    float* out = (float*)d_out;

    cudaFuncSetAttribute(argmin_hmma_kernel,
                         cudaFuncAttributeMaxDynamicSharedMemorySize, SMEM_TOTAL);

    init_kernel<<<Nrows / 256, 256>>>();
    convert_kernel<<<dim3(Tt / 32, Cc / 32, Bb), dim3(32, 8)>>>(feat);
    csq_kernel<<<Kk / 8, 256>>>(cent);
    argmin_hmma_kernel<<<GRID_MAIN, 256, SMEM_TOTAL>>>();
    rerank_kernel<<<Nrows / 8, 256>>>(cent);
    output_kernel<<<dim3(Tt / 32, Cc / 32, Bb), dim3(32, 8)>>>(feat, cent, out);
}

// round 14
// speedup vs baseline: 1.1551x; 1.1551x over previous
#include <cuda_runtime.h>
#include <cuda_bf16.h>
#include <cstdint>

// ---------------------------------------------------------------------------
// Problem constants
// ---------------------------------------------------------------------------
static constexpr int Bb = 16;
static constexpr int Cc = 1024;
static constexpr int Tt = 2048;
static constexpr int Kk = 4096;
static constexpr int Nrows = Bb * Tt;  // 32768

static constexpr float MARGIN = 2.0f;   // bf16-calibrated (proven exact R3/R7/R12)
static constexpr int   NCAND  = 128;

// Main GEMM tiling (R12 shape): CTA = 128 rows x 2048 cols (one K-half).
static constexpr int TM = 128;
static constexpr int TN = 128;
static constexpr int KHALF = 2048;
static constexpr int NKT = KHALF / TN;            // 16 k-tiles
static constexpr int NCH = 16;                    // 64-deep chunks per k-tile
static constexpr int NCHT = NKT * NCH;            // 256 stages

static constexpr int A_STAGE = TM * 128;          // 16KB (128B rows, 64 bf16)
static constexpr int STAGE_BYTES = 2 * A_STAGE;   // 32KB
static constexpr uint32_t SMEM_CSQ = 3 * STAGE_BYTES;            // 98304
static constexpr uint32_t SMEM_TOTAL = SMEM_CSQ + KHALF * 4;     // 104KB

// ---------------------------------------------------------------------------
// Device scratch (no cudaMalloc allowed)
// ---------------------------------------------------------------------------
__device__ __align__(1024) __nv_bfloat16 g_xb[(size_t)Nrows * Cc];  // transposed bf16 x
__device__ __align__(1024) float         g_xf[(size_t)Nrows * Cc];  // transposed fp32 x
__device__ __align__(1024) __nv_bfloat16 g_cb[(size_t)Kk * Cc];     // bf16 centroids
__device__ float g_csq[Kk];
__device__ unsigned long long g_cand[Nrows][NCAND];
__device__ int g_ccount[Nrows];
__device__ int g_amin[Nrows];

// ---------------------------------------------------------------------------
// Helpers
// ---------------------------------------------------------------------------
__device__ __forceinline__ uint32_t smem_u32(const void* p) {
    uint32_t a;
    asm("{ .reg .u64 t; cvta.to.shared.u64 t, %1; cvt.u32.u64 %0, t; }" : "=r"(a) : "l"(p));
    return a;
}
__device__ __forceinline__ unsigned enc(float f) {
    unsigned u = __float_as_uint(f);
    return u ^ ((unsigned)((int)u >> 31) | 0x80000000u);
}
__device__ __forceinline__ float dec(unsigned u) {
    unsigned m = ((int)u >= 0) ? 0xFFFFFFFFu : 0x80000000u;
    return __uint_as_float(u ^ m);
}

#define CP16(sm, gp) \
    asm volatile("cp.async.cg.shared.global [%0], [%1], 16;" :: "r"(sm), "l"(gp))
#define CP_COMMIT() asm volatile("cp.async.commit_group;" ::: "memory")
#define CP_WAIT1()  asm volatile("cp.async.wait_group 1;" ::: "memory")

#define LDSM4(f, a) \
    asm volatile("ldmatrix.sync.aligned.m8n8.x4.shared.b16 {%0,%1,%2,%3}, [%4];" \
        : "=r"((f)[0]), "=r"((f)[1]), "=r"((f)[2]), "=r"((f)[3]) : "r"(a))

#define MMA16816(c, a, b0v, b1v)                                               \
    asm volatile("mma.sync.aligned.m16n8k16.row.col.f32.bf16.bf16.f32 "        \
        "{%0,%1,%2,%3},{%4,%5,%6,%7},{%8,%9},{%0,%1,%2,%3};"                   \
        : "+f"((c)[0]), "+f"((c)[1]), "+f"((c)[2]), "+f"((c)[3])               \
        : "r"((a)[0]), "r"((a)[1]), "r"((a)[2]), "r"((a)[3]),                  \
          "r"(b0v), "r"(b1v))

// ---------------------------------------------------------------------------
// Kernel 0: zero candidate counters (graph replays need re-zero every launch)
// ---------------------------------------------------------------------------
__global__ void init_kernel() {
    g_ccount[blockIdx.x * 256 + threadIdx.x] = 0;
}

// ---------------------------------------------------------------------------
// Kernel 1: transpose + convert feature -> g_xf (fp32), g_xb (bf16)
// ---------------------------------------------------------------------------
__global__ void convert_kernel(const float* __restrict__ feat) {
    __shared__ float tile[32][33];
    const int t0 = blockIdx.x * 32, c0 = blockIdx.y * 32, b = blockIdx.z;
    const int tx = threadIdx.x, ty = threadIdx.y;
    #pragma unroll
    for (int cc = ty; cc < 32; cc += 8)
        tile[cc][tx] = feat[(size_t)b * Cc * Tt + (size_t)(c0 + cc) * Tt + t0 + tx];
    __syncthreads();
    #pragma unroll
    for (int tt = ty; tt < 32; tt += 8) {
        float v = tile[tx][tt];
        size_t off = (size_t)(b * Tt + t0 + tt) * Cc + c0 + tx;
        g_xf[off] = v;
        g_xb[off] = __float2bfloat16(v);
    }
}

// ---------------------------------------------------------------------------
// Kernel 2: csq (fp64 accum) + bf16 centroid conversion
// ---------------------------------------------------------------------------
__global__ void csq_kernel(const float* __restrict__ cent) {
    int k = blockIdx.x * 8 + (threadIdx.x >> 5);
    int lane = threadIdx.x & 31;
    const float* row = cent + (size_t)k * Cc;
    double s = 0.0;
    #pragma unroll
    for (int i = 0; i < Cc / 128; i++) {
        float4 v = *reinterpret_cast<const float4*>(row + i * 128 + lane * 4);
        s += (double)v.x * v.x + (double)v.y * v.y + (double)v.z * v.z + (double)v.w * v.w;
        __nv_bfloat162 p0 = __floats2bfloat162_rn(v.x, v.y);
        __nv_bfloat162 p1 = __floats2bfloat162_rn(v.z, v.w);
        *reinterpret_cast<__nv_bfloat162*>(&g_cb[(size_t)k * Cc + i * 128 + lane * 4]) = p0;
        *reinterpret_cast<__nv_bfloat162*>(&g_cb[(size_t)k * Cc + i * 128 + lane * 4 + 2]) = p1;
    }
    #pragma unroll
    for (int off = 16; off; off >>= 1) s += __shfl_down_sync(0xffffffffu, s, off);
    if (lane == 0) g_csq[k] = (float)s;
}

// ---------------------------------------------------------------------------
// Kernel 3: HMMA GEMM + shortlist argmin (R12 pipeline, smem csq).
// 8 warps 2x4, warp tile 64x32, 64-deep stages, 3-buffer cp.async pipeline.
// Single-pass epilogue: per-quad running min carried across k-tiles.
// ---------------------------------------------------------------------------
__global__ __launch_bounds__(256, 2)
void argmin_hmma_kernel() {
    extern __shared__ char smem[];
    const uint32_t sb = smem_u32(smem);
    float* csqs = (float*)(smem + SMEM_CSQ);

    const int tid  = threadIdx.x;
    const int lane = tid & 31;
    const int wid  = tid >> 5;
    const int wm0  = (wid & 1) * 64;
    const int wn0  = (wid >> 1) * 32;

    const int rowbase = (blockIdx.x >> 1) * TM;
    const int kbase   = (blockIdx.x & 1) * KHALF;

    const char* Ag0 = (const char*)g_xb + (size_t)rowbase * 2048;
    const char* Bg0 = (const char*)g_cb + (size_t)kbase * 2048;

    // preload this K-half's csq slice into smem (2048 floats)
    #pragma unroll
    for (int i = 0; i < KHALF / 256; i++)
        csqs[tid + i * 256] = g_csq[kbase + tid + i * 256];

    const int arow  = lane & 15, ahalf = lane >> 4;
    const int browl = (lane & 7) + ((lane >> 4) << 3);
    const int bhalf = (lane >> 3) & 1;

    auto load_stage = [&](int s, int bf) {
        if (s < NCHT) {
            const int kt = s >> 4, cc = s & 15;
            const uint32_t st = sb + bf * STAGE_BYTES;
            const char* ag = Ag0 + cc * 128;
            const char* bg = Bg0 + (size_t)(kt * TN) * 2048 + cc * 128;
            #pragma unroll
            for (int j = 0; j < 4; j++) {
                const int ch = tid + j * 256;
                const int r = ch >> 3, c = ch & 7;
                CP16(st + r * 128 + ((c ^ (r & 7)) << 4), ag + (size_t)r * 2048 + c * 16);
            }
            const uint32_t bst = st + A_STAGE;
            #pragma unroll
            for (int j = 0; j < 4; j++) {
                const int ch = tid + j * 256;
                const int r = ch >> 3, c = ch & 7;
                CP16(bst + r * 128 + ((c ^ (r & 7)) << 4), bg + (size_t)r * 2048 + c * 16);
            }
        }
        CP_COMMIT();
    };

    load_stage(0, 0); load_stage(1, 1);
    int buf = 0, nbuf = 2;
    __syncthreads();   // csqs visible to all warps

    float runmin[4][2];
    #pragma unroll
    for (int mi = 0; mi < 4; mi++) { runmin[mi][0] = 3.0e38f; runmin[mi][1] = 3.0e38f; }

    for (int kt = 0; kt < NKT; ++kt) {
        float acc[4][4][4];
        #pragma unroll
        for (int mi = 0; mi < 4; mi++)
            #pragma unroll
            for (int ni = 0; ni < 4; ni++)
                #pragma unroll
                for (int q = 0; q < 4; q++) acc[mi][ni][q] = 0.0f;

        for (int cc = 0; cc < NCH; ++cc) {
            const int s = (kt << 4) + cc;
            CP_WAIT1();
            __syncthreads();
            load_stage(s + 2, nbuf);
            const uint32_t st = sb + buf * STAGE_BYTES;
            buf = (buf + 1 == 3) ? 0 : buf + 1;
            nbuf = (nbuf + 1 == 3) ? 0 : nbuf + 1;

            #pragma unroll
            for (int ks = 0; ks < 4; ++ks) {
                uint32_t af[4][4];
                #pragma unroll
                for (int mi = 0; mi < 4; mi++) {
                    const int r = wm0 + mi * 16 + arow;
                    LDSM4(af[mi], st + r * 128 + ((((ks << 1) + ahalf) ^ (r & 7)) << 4));
                }
                uint32_t bfr[2][4];
                #pragma unroll
                for (int p = 0; p < 2; p++) {
                    const int r = wn0 + p * 16 + browl;
                    LDSM4(bfr[p], st + A_STAGE + r * 128 +
                                  ((((ks << 1) + bhalf) ^ (r & 7)) << 4));
                }
                #pragma unroll
                for (int mi = 0; mi < 4; mi++)
                    #pragma unroll
                    for (int ni = 0; ni < 4; ni++)
                        MMA16816(acc[mi][ni], af[mi],
                                 bfr[ni >> 1][(ni & 1) * 2], bfr[ni >> 1][(ni & 1) * 2 + 1]);
            }
        }

        // ---- single-pass epilogue: quad running min + direct append ----
        float csqv[8];
        #pragma unroll
        for (int ni = 0; ni < 4; ni++)
            #pragma unroll
            for (int c = 0; c < 2; c++)
                csqv[ni * 2 + c] =
                    csqs[kt * TN + wn0 + ni * 8 + (lane & 3) * 2 + c];

        #pragma unroll
        for (int mi = 0; mi < 4; mi++)
            #pragma unroll
            for (int rh = 0; rh < 2; rh++) {
                float d[8];
                float dmin = 3.0e38f;
                #pragma unroll
                for (int j = 0; j < 8; j++) {
                    d[j] = fmaf(acc[mi][j >> 1][rh * 2 + (j & 1)], -2.0f, csqv[j]);
                    dmin = fminf(dmin, d[j]);
                }
                dmin = fminf(dmin, __shfl_xor_sync(0xffffffffu, dmin, 1));
                dmin = fminf(dmin, __shfl_xor_sync(0xffffffffu, dmin, 2));
                const float thr = fminf(runmin[mi][rh], dmin) + MARGIN;
                runmin[mi][rh] = fminf(runmin[mi][rh], dmin);
                const int row = rowbase + wm0 + mi * 16 + (lane >> 2) + rh * 8;
                #pragma unroll
                for (int j = 0; j < 8; j++) {
                    if (d[j] < thr) {
                        const int kcol =
                            kbase + kt * TN + wn0 + (j >> 1) * 8 + (lane & 3) * 2 + (j & 1);
                        const int idx = atomicAdd(&g_ccount[row], 1);
                        if (idx < NCAND)
                            g_cand[row][idx] =
                                ((unsigned long long)enc(d[j]) << 32) | (unsigned)kcol;
                    }
                }
            }
    }
}

// ---------------------------------------------------------------------------
// Kernel 4: exact fp32 re-rank (one warp per row).
// Fast path: if exactly ONE candidate lies within MARGIN of the best approx
// key, the margin guarantee (2e <= MARGIN) proves it is the exact argmin --
// no fp32 dot needed. Otherwise exact-dot re-rank of the passers.
// ---------------------------------------------------------------------------
__global__ __launch_bounds__(256)
void rerank_kernel(const float* __restrict__ cent) {
    const int lane = threadIdx.x & 31;
    const int row = blockIdx.x * 8 + (threadIdx.x >> 5);
    const int n = g_ccount[row];

    unsigned long long best = ~0ULL;
    if (n <= NCAND) {
        // min approx key over candidates (lanes cover 4 strided slots each)
        unsigned long long mn = ~0ULL;
        #pragma unroll
        for (int h = 0; h < 4; h++) {
            const int i = lane + h * 32;
            if (i < n) {
                unsigned long long v = g_cand[row][i];
                mn = (v < mn) ? v : mn;
            }
        }
        #pragma unroll
        for (int off = 16; off; off >>= 1) {
            unsigned long long o = __shfl_xor_sync(0xffffffffu, mn, off);
            mn = (o < mn) ? o : mn;
        }
        const unsigned thrk = enc(dec((unsigned)(mn >> 32)) + MARGIN);

        // count passers (warp-parallel over slots)
        int mycnt = 0;
        #pragma unroll
        for (int h = 0; h < 4; h++) {
            const int i = lane + h * 32;
            if (i < n && (unsigned)(g_cand[row][i] >> 32) < thrk) mycnt++;
        }
        #pragma unroll
        for (int off = 16; off; off >>= 1)
            mycnt += __shfl_xor_sync(0xffffffffu, mycnt, off);

        if (mycnt == 1) {
            // single passer is necessarily the min key itself -> exact argmin
            if (lane == 0) g_amin[row] = (int)(mn & 0xffffffffu);
            return;
        }

        // >=2 passers: exact fp32 re-rank of passers
        float4 xv[8];
        const float4* xr = reinterpret_cast<const float4*>(g_xf + (size_t)row * Cc);
        #pragma unroll
        for (int i = 0; i < 8; i++) xv[i] = xr[i * 32 + lane];

        for (int i = 0; i < n; i++) {
            const unsigned long long ki = g_cand[row][i];   // broadcast load
            if ((unsigned)(ki >> 32) >= thrk) continue;
            const int k = (int)(ki & 0xffffffffu);
            const float4* crp = reinterpret_cast<const float4*>(cent + (size_t)k * Cc);
            float s = 0.f;
            #pragma unroll
            for (int i2 = 0; i2 < 8; i2++) {
                float4 cv = crp[i2 * 32 + lane];
                s = fmaf(xv[i2].x, cv.x, s); s = fmaf(xv[i2].y, cv.y, s);
                s = fmaf(xv[i2].z, cv.z, s); s = fmaf(xv[i2].w, cv.w, s);
            }
            #pragma unroll
            for (int off = 16; off; off >>= 1) s += __shfl_xor_sync(0xffffffffu, s, off);
            const float dd = fmaf(s, -2.0f, g_csq[k]);
            unsigned long long key = ((unsigned long long)enc(dd) << 32) | (unsigned)k;
            best = (key < best) ? key : best;
        }
    } else {
        // overflow fallback: exact scan over all K
        float4 xv[8];
        const float4* xr = reinterpret_cast<const float4*>(g_xf + (size_t)row * Cc);
        #pragma unroll
        for (int i = 0; i < 8; i++) xv[i] = xr[i * 32 + lane];

        for (int k = 0; k < Kk; k++) {
            const float4* crp = reinterpret_cast<const float4*>(cent + (size_t)k * Cc);
            float s = 0.f;
            #pragma unroll
            for (int i2 = 0; i2 < 8; i2++) {
                float4 cv = crp[i2 * 32 + lane];
                s = fmaf(xv[i2].x, cv.x, s); s = fmaf(xv[i2].y, cv.y, s);
                s = fmaf(xv[i2].z, cv.z, s); s = fmaf(xv[i2].w, cv.w, s);
            }
            #pragma unroll
            for (int off = 16; off; off >>= 1) s += __shfl_xor_sync(0xffffffffu, s, off);
            const float dd = fmaf(s, -2.0f, g_csq[k]);
            unsigned long long key = ((unsigned long long)enc(dd) << 32) | (unsigned)k;
            best = (key < best) ? key : best;
        }
    }
    if (lane == 0) g_amin[row] = (int)(best & 0xffffffffu);
}

// ---------------------------------------------------------------------------
// Kernel 5: output = feature - centroid[amin]
// ---------------------------------------------------------------------------
__global__ void output_kernel(const float* __restrict__ feat,
                              const float* __restrict__ cent,
                              float* __restrict__ out) {
    __shared__ float ctile[32][33];
    const int t0 = blockIdx.x * 32, c0 = blockIdx.y * 32, b = blockIdx.z;
    const int tx = threadIdx.x, ty = threadIdx.y;
    #pragma unroll
    for (int tt = ty; tt < 32; tt += 8) {
        int kidx = g_amin[b * Tt + t0 + tt];
        ctile[tt][tx] = cent[(size_t)kidx * Cc + c0 + tx];
    }
    __syncthreads();
    #pragma unroll
    for (int cc = ty; cc < 32; cc += 8) {
        size_t off = (size_t)b * Cc * Tt + (size_t)(c0 + cc) * Tt + t0 + tx;
        out[off] = feat[off] - ctile[tx][cc];
    }
}

// ---------------------------------------------------------------------------
extern "C" void kernel_launch(void* const* d_in, const int* in_sizes, int n_in,
                              void* d_out, int out_size) {
    const float* feat = (const float*)d_in[0];
    const float* cent = (const float*)d_in[1];
    float* out = (float*)d_out;

    cudaFuncSetAttribute(argmin_hmma_kernel,
                         cudaFuncAttributeMaxDynamicSharedMemorySize, SMEM_TOTAL);

    init_kernel<<<Nrows / 256, 256>>>();
    convert_kernel<<<dim3(Tt / 32, Cc / 32, Bb), dim3(32, 8)>>>(feat);
    csq_kernel<<<Kk / 8, 256>>>(cent);
    argmin_hmma_kernel<<<(Nrows / TM) * 2, 256, SMEM_TOTAL>>>();
    rerank_kernel<<<Nrows / 8, 256>>>(cent);
    output_kernel<<<dim3(Tt / 32, Cc / 32, Bb), dim3(32, 8)>>>(feat, cent, out);
}

// round 15
// speedup vs baseline: 1.1897x; 1.0299x over previous
#include <cuda_runtime.h>
#include <cuda_bf16.h>
#include <cstdint>

// ---------------------------------------------------------------------------
// Problem constants
// ---------------------------------------------------------------------------
static constexpr int Bb = 16;
static constexpr int Cc = 1024;
static constexpr int Tt = 2048;
static constexpr int Kk = 4096;
static constexpr int Nrows = Bb * Tt;  // 32768

static constexpr float MARGIN = 2.0f;   // bf16-calibrated (proven exact R3/R7/R12/R14)
static constexpr int   NCAND  = 128;

// Main GEMM tiling (R12/R14 shape): CTA = 128 rows x 2048 cols (one K-half).
static constexpr int TM = 128;
static constexpr int TN = 128;
static constexpr int KHALF = 2048;
static constexpr int NKT = KHALF / TN;            // 16 k-tiles
static constexpr int NCH = 16;                    // 64-deep chunks per k-tile
static constexpr int NCHT = NKT * NCH;            // 256 stages

static constexpr int A_STAGE = TM * 128;          // 16KB (128B rows, 64 bf16)
static constexpr int STAGE_BYTES = 2 * A_STAGE;   // 32KB
static constexpr uint32_t SMEM_CSQ = 3 * STAGE_BYTES;            // 98304
static constexpr uint32_t SMEM_TOTAL = SMEM_CSQ + KHALF * 4;     // 104KB

// ---------------------------------------------------------------------------
// Device scratch (no cudaMalloc allowed)
// ---------------------------------------------------------------------------
__device__ __align__(1024) __nv_bfloat16 g_xb[(size_t)Nrows * Cc];  // transposed bf16 x
__device__ __align__(1024) float         g_xf[(size_t)Nrows * Cc];  // transposed fp32 x
__device__ __align__(1024) __nv_bfloat16 g_cb[(size_t)Kk * Cc];     // bf16 centroids
__device__ float g_csq[Kk];
__device__ unsigned long long g_cand[Nrows][NCAND];
__device__ int g_ccount[Nrows];
__device__ int g_amin[Nrows];

// ---------------------------------------------------------------------------
// Helpers
// ---------------------------------------------------------------------------
__device__ __forceinline__ uint32_t smem_u32(const void* p) {
    uint32_t a;
    asm("{ .reg .u64 t; cvta.to.shared.u64 t, %1; cvt.u32.u64 %0, t; }" : "=r"(a) : "l"(p));
    return a;
}
__device__ __forceinline__ unsigned enc(float f) {
    unsigned u = __float_as_uint(f);
    return u ^ ((unsigned)((int)u >> 31) | 0x80000000u);
}
__device__ __forceinline__ float dec(unsigned u) {
    unsigned m = ((int)u >= 0) ? 0xFFFFFFFFu : 0x80000000u;
    return __uint_as_float(u ^ m);
}

#define CP16(sm, gp) \
    asm volatile("cp.async.cg.shared.global [%0], [%1], 16;" :: "r"(sm), "l"(gp))
#define CP_COMMIT() asm volatile("cp.async.commit_group;" ::: "memory")
#define CP_WAIT1()  asm volatile("cp.async.wait_group 1;" ::: "memory")

#define LDSM4(f, a) \
    asm volatile("ldmatrix.sync.aligned.m8n8.x4.shared.b16 {%0,%1,%2,%3}, [%4];" \
        : "=r"((f)[0]), "=r"((f)[1]), "=r"((f)[2]), "=r"((f)[3]) : "r"(a))

#define MMA16816(c, a, b0v, b1v)                                               \
    asm volatile("mma.sync.aligned.m16n8k16.row.col.f32.bf16.bf16.f32 "        \
        "{%0,%1,%2,%3},{%4,%5,%6,%7},{%8,%9},{%0,%1,%2,%3};"                   \
        : "+f"((c)[0]), "+f"((c)[1]), "+f"((c)[2]), "+f"((c)[3])               \
        : "r"((a)[0]), "r"((a)[1]), "r"((a)[2]), "r"((a)[3]),                  \
          "r"(b0v), "r"(b1v))

// ---------------------------------------------------------------------------
// Kernel 1: transpose + convert feature -> g_xf (fp32), g_xb (bf16).
// 64x64 tiles, float4 loads, float4 / packed-uint2 stores.
// Also zeroes g_ccount (blocks with blockIdx.y == 0), replacing init_kernel.
// ---------------------------------------------------------------------------
__global__ __launch_bounds__(256)
void convert_kernel(const float* __restrict__ feat) {
    __shared__ float tile[64][65];
    const int t0 = blockIdx.x * 64, c0 = blockIdx.y * 64, b = blockIdx.z;
    const int tid = threadIdx.x;

    if (blockIdx.y == 0 && tid < 64)
        g_ccount[b * Tt + t0 + tid] = 0;

    // load 64 c-rows x 64 t (coalesced float4 along t)
    #pragma unroll
    for (int i = 0; i < 4; i++) {
        const int idx = tid + i * 256;        // 0..1023
        const int cc = idx >> 4, f4 = idx & 15;
        const float4 v = *reinterpret_cast<const float4*>(
            &feat[(size_t)b * Cc * Tt + (size_t)(c0 + cc) * Tt + t0 + f4 * 4]);
        tile[cc][f4 * 4 + 0] = v.x; tile[cc][f4 * 4 + 1] = v.y;
        tile[cc][f4 * 4 + 2] = v.z; tile[cc][f4 * 4 + 3] = v.w;
    }
    __syncthreads();

    // write transposed: per t-row, 64 c values (float4 + packed 4xbf16)
    #pragma unroll
    for (int i = 0; i < 4; i++) {
        const int idx = tid + i * 256;
        const int tt = idx >> 4, f4 = idx & 15;
        float4 v;
        v.x = tile[f4 * 4 + 0][tt]; v.y = tile[f4 * 4 + 1][tt];
        v.z = tile[f4 * 4 + 2][tt]; v.w = tile[f4 * 4 + 3][tt];
        const size_t row = (size_t)(b * Tt + t0 + tt);
        *reinterpret_cast<float4*>(&g_xf[row * Cc + c0 + f4 * 4]) = v;
        uint2 p;
        p.x = __uint_as_float(0), p.y = 0;  // placeholder init (overwritten below)
        __nv_bfloat162 lo = __floats2bfloat162_rn(v.x, v.y);
        __nv_bfloat162 hi = __floats2bfloat162_rn(v.z, v.w);
        p.x = *reinterpret_cast<uint32_t*>(&lo);
        p.y = *reinterpret_cast<uint32_t*>(&hi);
        *reinterpret_cast<uint2*>(&g_xb[row * Cc + c0 + f4 * 4]) = p;
    }
}

// ---------------------------------------------------------------------------
// Kernel 2: csq (fp64 accum) + bf16 centroid conversion
// ---------------------------------------------------------------------------
__global__ void csq_kernel(const float* __restrict__ cent) {
    int k = blockIdx.x * 8 + (threadIdx.x >> 5);
    int lane = threadIdx.x & 31;
    const float* row = cent + (size_t)k * Cc;
    double s = 0.0;
    #pragma unroll
    for (int i = 0; i < Cc / 128; i++) {
        float4 v = *reinterpret_cast<const float4*>(row + i * 128 + lane * 4);
        s += (double)v.x * v.x + (double)v.y * v.y + (double)v.z * v.z + (double)v.w * v.w;
        __nv_bfloat162 p0 = __floats2bfloat162_rn(v.x, v.y);
        __nv_bfloat162 p1 = __floats2bfloat162_rn(v.z, v.w);
        *reinterpret_cast<__nv_bfloat162*>(&g_cb[(size_t)k * Cc + i * 128 + lane * 4]) = p0;
        *reinterpret_cast<__nv_bfloat162*>(&g_cb[(size_t)k * Cc + i * 128 + lane * 4 + 2]) = p1;
    }
    #pragma unroll
    for (int off = 16; off; off >>= 1) s += __shfl_down_sync(0xffffffffu, s, off);
    if (lane == 0) g_csq[k] = (float)s;
}

// ---------------------------------------------------------------------------
// Kernel 3: HMMA GEMM + shortlist argmin (identical to R14 — banked WIN).
// ---------------------------------------------------------------------------
__global__ __launch_bounds__(256, 2)
void argmin_hmma_kernel() {
    extern __shared__ char smem[];
    const uint32_t sb = smem_u32(smem);
    float* csqs = (float*)(smem + SMEM_CSQ);

    const int tid  = threadIdx.x;
    const int lane = tid & 31;
    const int wid  = tid >> 5;
    const int wm0  = (wid & 1) * 64;
    const int wn0  = (wid >> 1) * 32;

    const int rowbase = (blockIdx.x >> 1) * TM;
    const int kbase   = (blockIdx.x & 1) * KHALF;

    const char* Ag0 = (const char*)g_xb + (size_t)rowbase * 2048;
    const char* Bg0 = (const char*)g_cb + (size_t)kbase * 2048;

    #pragma unroll
    for (int i = 0; i < KHALF / 256; i++)
        csqs[tid + i * 256] = g_csq[kbase + tid + i * 256];

    const int arow  = lane & 15, ahalf = lane >> 4;
    const int browl = (lane & 7) + ((lane >> 4) << 3);
    const int bhalf = (lane >> 3) & 1;

    auto load_stage = [&](int s, int bf) {
        if (s < NCHT) {
            const int kt = s >> 4, cc = s & 15;
            const uint32_t st = sb + bf * STAGE_BYTES;
            const char* ag = Ag0 + cc * 128;
            const char* bg = Bg0 + (size_t)(kt * TN) * 2048 + cc * 128;
            #pragma unroll
            for (int j = 0; j < 4; j++) {
                const int ch = tid + j * 256;
                const int r = ch >> 3, c = ch & 7;
                CP16(st + r * 128 + ((c ^ (r & 7)) << 4), ag + (size_t)r * 2048 + c * 16);
            }
            const uint32_t bst = st + A_STAGE;
            #pragma unroll
            for (int j = 0; j < 4; j++) {
                const int ch = tid + j * 256;
                const int r = ch >> 3, c = ch & 7;
                CP16(bst + r * 128 + ((c ^ (r & 7)) << 4), bg + (size_t)r * 2048 + c * 16);
            }
        }
        CP_COMMIT();
    };

    load_stage(0, 0); load_stage(1, 1);
    int buf = 0, nbuf = 2;
    __syncthreads();   // csqs visible to all warps

    float runmin[4][2];
    #pragma unroll
    for (int mi = 0; mi < 4; mi++) { runmin[mi][0] = 3.0e38f; runmin[mi][1] = 3.0e38f; }

    for (int kt = 0; kt < NKT; ++kt) {
        float acc[4][4][4];
        #pragma unroll
        for (int mi = 0; mi < 4; mi++)
            #pragma unroll
            for (int ni = 0; ni < 4; ni++)
                #pragma unroll
                for (int q = 0; q < 4; q++) acc[mi][ni][q] = 0.0f;

        for (int cc = 0; cc < NCH; ++cc) {
            const int s = (kt << 4) + cc;
            CP_WAIT1();
            __syncthreads();
            load_stage(s + 2, nbuf);
            const uint32_t st = sb + buf * STAGE_BYTES;
            buf = (buf + 1 == 3) ? 0 : buf + 1;
            nbuf = (nbuf + 1 == 3) ? 0 : nbuf + 1;

            #pragma unroll
            for (int ks = 0; ks < 4; ++ks) {
                uint32_t af[4][4];
                #pragma unroll
                for (int mi = 0; mi < 4; mi++) {
                    const int r = wm0 + mi * 16 + arow;
                    LDSM4(af[mi], st + r * 128 + ((((ks << 1) + ahalf) ^ (r & 7)) << 4));
                }
                uint32_t bfr[2][4];
                #pragma unroll
                for (int p = 0; p < 2; p++) {
                    const int r = wn0 + p * 16 + browl;
                    LDSM4(bfr[p], st + A_STAGE + r * 128 +
                                  ((((ks << 1) + bhalf) ^ (r & 7)) << 4));
                }
                #pragma unroll
                for (int mi = 0; mi < 4; mi++)
                    #pragma unroll
                    for (int ni = 0; ni < 4; ni++)
                        MMA16816(acc[mi][ni], af[mi],
                                 bfr[ni >> 1][(ni & 1) * 2], bfr[ni >> 1][(ni & 1) * 2 + 1]);
            }
        }

        // ---- single-pass epilogue: quad running min + direct append ----
        float csqv[8];
        #pragma unroll
        for (int ni = 0; ni < 4; ni++)
            #pragma unroll
            for (int c = 0; c < 2; c++)
                csqv[ni * 2 + c] =
                    csqs[kt * TN + wn0 + ni * 8 + (lane & 3) * 2 + c];

        #pragma unroll
        for (int mi = 0; mi < 4; mi++)
            #pragma unroll
            for (int rh = 0; rh < 2; rh++) {
                float d[8];
                float dmin = 3.0e38f;
                #pragma unroll
                for (int j = 0; j < 8; j++) {
                    d[j] = fmaf(acc[mi][j >> 1][rh * 2 + (j & 1)], -2.0f, csqv[j]);
                    dmin = fminf(dmin, d[j]);
                }
                dmin = fminf(dmin, __shfl_xor_sync(0xffffffffu, dmin, 1));
                dmin = fminf(dmin, __shfl_xor_sync(0xffffffffu, dmin, 2));
                const float thr = fminf(runmin[mi][rh], dmin) + MARGIN;
                runmin[mi][rh] = fminf(runmin[mi][rh], dmin);
                const int row = rowbase + wm0 + mi * 16 + (lane >> 2) + rh * 8;
                #pragma unroll
                for (int j = 0; j < 8; j++) {
                    if (d[j] < thr) {
                        const int kcol =
                            kbase + kt * TN + wn0 + (j >> 1) * 8 + (lane & 3) * 2 + (j & 1);
                        const int idx = atomicAdd(&g_ccount[row], 1);
                        if (idx < NCAND)
                            g_cand[row][idx] =
                                ((unsigned long long)enc(d[j]) << 32) | (unsigned)kcol;
                    }
                }
            }
    }
}

// ---------------------------------------------------------------------------
// Kernel 4: exact fp32 re-rank (one warp per row) with single-passer fast path.
// ---------------------------------------------------------------------------
__global__ __launch_bounds__(256)
void rerank_kernel(const float* __restrict__ cent) {
    const int lane = threadIdx.x & 31;
    const int row = blockIdx.x * 8 + (threadIdx.x >> 5);
    const int n = g_ccount[row];

    unsigned long long best = ~0ULL;
    if (n <= NCAND) {
        unsigned long long mn = ~0ULL;
        #pragma unroll
        for (int h = 0; h < 4; h++) {
            const int i = lane + h * 32;
            if (i < n) {
                unsigned long long v = g_cand[row][i];
                mn = (v < mn) ? v : mn;
            }
        }
        #pragma unroll
        for (int off = 16; off; off >>= 1) {
            unsigned long long o = __shfl_xor_sync(0xffffffffu, mn, off);
            mn = (o < mn) ? o : mn;
        }
        const unsigned thrk = enc(dec((unsigned)(mn >> 32)) + MARGIN);

        int mycnt = 0;
        #pragma unroll
        for (int h = 0; h < 4; h++) {
            const int i = lane + h * 32;
            if (i < n && (unsigned)(g_cand[row][i] >> 32) < thrk) mycnt++;
        }
        #pragma unroll
        for (int off = 16; off; off >>= 1)
            mycnt += __shfl_xor_sync(0xffffffffu, mycnt, off);

        if (mycnt == 1) {
            if (lane == 0) g_amin[row] = (int)(mn & 0xffffffffu);
            return;
        }

        float4 xv[8];
        const float4* xr = reinterpret_cast<const float4*>(g_xf + (size_t)row * Cc);
        #pragma unroll
        for (int i = 0; i < 8; i++) xv[i] = xr[i * 32 + lane];

        for (int i = 0; i < n; i++) {
            const unsigned long long ki = g_cand[row][i];   // broadcast load
            if ((unsigned)(ki >> 32) >= thrk) continue;
            const int k = (int)(ki & 0xffffffffu);
            const float4* crp = reinterpret_cast<const float4*>(cent + (size_t)k * Cc);
            float s = 0.f;
            #pragma unroll
            for (int i2 = 0; i2 < 8; i2++) {
                float4 cv = crp[i2 * 32 + lane];
                s = fmaf(xv[i2].x, cv.x, s); s = fmaf(xv[i2].y, cv.y, s);
                s = fmaf(xv[i2].z, cv.z, s); s = fmaf(xv[i2].w, cv.w, s);
            }
            #pragma unroll
            for (int off = 16; off; off >>= 1) s += __shfl_xor_sync(0xffffffffu, s, off);
            const float dd = fmaf(s, -2.0f, g_csq[k]);
            unsigned long long key = ((unsigned long long)enc(dd) << 32) | (unsigned)k;
            best = (key < best) ? key : best;
        }
    } else {
        float4 xv[8];
        const float4* xr = reinterpret_cast<const float4*>(g_xf + (size_t)row * Cc);
        #pragma unroll
        for (int i = 0; i < 8; i++) xv[i] = xr[i * 32 + lane];

        for (int k = 0; k < Kk; k++) {
            const float4* crp = reinterpret_cast<const float4*>(cent + (size_t)k * Cc);
            float s = 0.f;
            #pragma unroll
            for (int i2 = 0; i2 < 8; i2++) {
                float4 cv = crp[i2 * 32 + lane];
                s = fmaf(xv[i2].x, cv.x, s); s = fmaf(xv[i2].y, cv.y, s);
                s = fmaf(xv[i2].z, cv.z, s); s = fmaf(xv[i2].w, cv.w, s);
            }
            #pragma unroll
            for (int off = 16; off; off >>= 1) s += __shfl_xor_sync(0xffffffffu, s, off);
            const float dd = fmaf(s, -2.0f, g_csq[k]);
            unsigned long long key = ((unsigned long long)enc(dd) << 32) | (unsigned)k;
            best = (key < best) ? key : best;
        }
    }
    if (lane == 0) g_amin[row] = (int)(best & 0xffffffffu);
}

// ---------------------------------------------------------------------------
// Kernel 5: output = feature - centroid[amin]
// ---------------------------------------------------------------------------
__global__ void output_kernel(const float* __restrict__ feat,
                              const float* __restrict__ cent,
                              float* __restrict__ out) {
    __shared__ float ctile[32][33];
    const int t0 = blockIdx.x * 32, c0 = blockIdx.y * 32, b = blockIdx.z;
    const int tx = threadIdx.x, ty = threadIdx.y;
    #pragma unroll
    for (int tt = ty; tt < 32; tt += 8) {
        int kidx = g_amin[b * Tt + t0 + tt];
        ctile[tt][tx] = cent[(size_t)kidx * Cc + c0 + tx];
    }
    __syncthreads();
    #pragma unroll
    for (int cc = ty; cc < 32; cc += 8) {
        size_t off = (size_t)b * Cc * Tt + (size_t)(c0 + cc) * Tt + t0 + tx;
        out[off] = feat[off] - ctile[tx][cc];
    }
}

// ---------------------------------------------------------------------------
extern "C" void kernel_launch(void* const* d_in, const int* in_sizes, int n_in,
                              void* d_out, int out_size) {
    const float* feat = (const float*)d_in[0];
    const float* cent = (const float*)d_in[1];
    float* out = (float*)d_out;

    cudaFuncSetAttribute(argmin_hmma_kernel,
                         cudaFuncAttributeMaxDynamicSharedMemorySize, SMEM_TOTAL);

    convert_kernel<<<dim3(Tt / 64, Cc / 64, Bb), 256>>>(feat);
    csq_kernel<<<Kk / 8, 256>>>(cent);
    argmin_hmma_kernel<<<(Nrows / TM) * 2, 256, SMEM_TOTAL>>>();
    rerank_kernel<<<Nrows / 8, 256>>>(cent);
    output_kernel<<<dim3(Tt / 32, Cc / 32, Bb), dim3(32, 8)>>>(feat, cent, out);
}

// round 16
// speedup vs baseline: 1.2564x; 1.0561x over previous
#include <cuda_runtime.h>
#include <cuda_bf16.h>
#include <cstdint>

// ---------------------------------------------------------------------------
// Problem constants
// ---------------------------------------------------------------------------
static constexpr int Bb = 16;
static constexpr int Cc = 1024;
static constexpr int Tt = 2048;
static constexpr int Kk = 4096;
static constexpr int Nrows = Bb * Tt;  // 32768

static constexpr float MARGIN = 2.0f;   // bf16-calibrated (proven exact R3/R7/R12/R14/R15)
static constexpr int   NCAND  = 128;

// Main GEMM tiling (R12/R14 shape): CTA = 128 rows x 2048 cols (one K-half).
static constexpr int TM = 128;
static constexpr int TN = 128;
static constexpr int KHALF = 2048;
static constexpr int NKT = KHALF / TN;            // 16 k-tiles
static constexpr int NCH = 16;                    // 64-deep chunks per k-tile
static constexpr int NCHT = NKT * NCH;            // 256 stages

static constexpr int A_STAGE = TM * 128;          // 16KB (128B rows, 64 bf16)
static constexpr int STAGE_BYTES = 2 * A_STAGE;   // 32KB
static constexpr uint32_t SMEM_CSQ = 3 * STAGE_BYTES;            // 98304
static constexpr uint32_t SMEM_TOTAL = SMEM_CSQ + KHALF * 4;     // 104KB

// ---------------------------------------------------------------------------
// Device scratch (no cudaMalloc allowed)
// ---------------------------------------------------------------------------
__device__ __align__(1024) __nv_bfloat16 g_xb[(size_t)Nrows * Cc];  // transposed bf16 x
__device__ __align__(1024) float         g_xf[(size_t)Nrows * Cc];  // transposed fp32 x
__device__ __align__(1024) __nv_bfloat16 g_cb[(size_t)Kk * Cc];     // bf16 centroids
__device__ float g_csq[Kk];
__device__ unsigned long long g_cand[Nrows][NCAND];
__device__ int g_ccount[Nrows];
__device__ int g_amin[Nrows];

// ---------------------------------------------------------------------------
// Helpers
// ---------------------------------------------------------------------------
__device__ __forceinline__ uint32_t smem_u32(const void* p) {
    uint32_t a;
    asm("{ .reg .u64 t; cvta.to.shared.u64 t, %1; cvt.u32.u64 %0, t; }" : "=r"(a) : "l"(p));
    return a;
}
__device__ __forceinline__ unsigned enc(float f) {
    unsigned u = __float_as_uint(f);
    return u ^ ((unsigned)((int)u >> 31) | 0x80000000u);
}
__device__ __forceinline__ float dec(unsigned u) {
    unsigned m = ((int)u >= 0) ? 0xFFFFFFFFu : 0x80000000u;
    return __uint_as_float(u ^ m);
}

#define CP16(sm, gp) \
    asm volatile("cp.async.cg.shared.global [%0], [%1], 16;" :: "r"(sm), "l"(gp))
#define CP_COMMIT() asm volatile("cp.async.commit_group;" ::: "memory")
#define CP_WAIT1()  asm volatile("cp.async.wait_group 1;" ::: "memory")

#define LDSM4(f, a) \
    asm volatile("ldmatrix.sync.aligned.m8n8.x4.shared.b16 {%0,%1,%2,%3}, [%4];" \
        : "=r"((f)[0]), "=r"((f)[1]), "=r"((f)[2]), "=r"((f)[3]) : "r"(a))

#define MMA16816(c, a, b0v, b1v)                                               \
    asm volatile("mma.sync.aligned.m16n8k16.row.col.f32.bf16.bf16.f32 "        \
        "{%0,%1,%2,%3},{%4,%5,%6,%7},{%8,%9},{%0,%1,%2,%3};"                   \
        : "+f"((c)[0]), "+f"((c)[1]), "+f"((c)[2]), "+f"((c)[3])               \
        : "r"((a)[0]), "r"((a)[1]), "r"((a)[2]), "r"((a)[3]),                  \
          "r"(b0v), "r"(b1v))

// ---------------------------------------------------------------------------
// Kernel 1: transpose + convert feature -> g_xf (fp32), g_xb (bf16).
// 64x64 tiles, float4 loads, float4 / packed-uint2 stores.
// Also zeroes g_ccount (blocks with blockIdx.y == 0).
// ---------------------------------------------------------------------------
__global__ __launch_bounds__(256)
void convert_kernel(const float* __restrict__ feat) {
    __shared__ float tile[64][65];
    const int t0 = blockIdx.x * 64, c0 = blockIdx.y * 64, b = blockIdx.z;
    const int tid = threadIdx.x;

    if (blockIdx.y == 0 && tid < 64)
        g_ccount[b * Tt + t0 + tid] = 0;

    #pragma unroll
    for (int i = 0; i < 4; i++) {
        const int idx = tid + i * 256;        // 0..1023
        const int cc = idx >> 4, f4 = idx & 15;
        const float4 v = *reinterpret_cast<const float4*>(
            &feat[(size_t)b * Cc * Tt + (size_t)(c0 + cc) * Tt + t0 + f4 * 4]);
        tile[cc][f4 * 4 + 0] = v.x; tile[cc][f4 * 4 + 1] = v.y;
        tile[cc][f4 * 4 + 2] = v.z; tile[cc][f4 * 4 + 3] = v.w;
    }
    __syncthreads();

    #pragma unroll
    for (int i = 0; i < 4; i++) {
        const int idx = tid + i * 256;
        const int tt = idx >> 4, f4 = idx & 15;
        float4 v;
        v.x = tile[f4 * 4 + 0][tt]; v.y = tile[f4 * 4 + 1][tt];
        v.z = tile[f4 * 4 + 2][tt]; v.w = tile[f4 * 4 + 3][tt];
        const size_t row = (size_t)(b * Tt + t0 + tt);
        *reinterpret_cast<float4*>(&g_xf[row * Cc + c0 + f4 * 4]) = v;
        __nv_bfloat162 lo = __floats2bfloat162_rn(v.x, v.y);
        __nv_bfloat162 hi = __floats2bfloat162_rn(v.z, v.w);
        uint2 p;
        p.x = *reinterpret_cast<uint32_t*>(&lo);
        p.y = *reinterpret_cast<uint32_t*>(&hi);
        *reinterpret_cast<uint2*>(&g_xb[row * Cc + c0 + f4 * 4]) = p;
    }
}

// ---------------------------------------------------------------------------
// Kernel 2: csq (fp64 accum) + bf16 centroid conversion
// ---------------------------------------------------------------------------
__global__ void csq_kernel(const float* __restrict__ cent) {
    int k = blockIdx.x * 8 + (threadIdx.x >> 5);
    int lane = threadIdx.x & 31;
    const float* row = cent + (size_t)k * Cc;
    double s = 0.0;
    #pragma unroll
    for (int i = 0; i < Cc / 128; i++) {
        float4 v = *reinterpret_cast<const float4*>(row + i * 128 + lane * 4);
        s += (double)v.x * v.x + (double)v.y * v.y + (double)v.z * v.z + (double)v.w * v.w;
        __nv_bfloat162 p0 = __floats2bfloat162_rn(v.x, v.y);
        __nv_bfloat162 p1 = __floats2bfloat162_rn(v.z, v.w);
        *reinterpret_cast<__nv_bfloat162*>(&g_cb[(size_t)k * Cc + i * 128 + lane * 4]) = p0;
        *reinterpret_cast<__nv_bfloat162*>(&g_cb[(size_t)k * Cc + i * 128 + lane * 4 + 2]) = p1;
    }
    #pragma unroll
    for (int off = 16; off; off >>= 1) s += __shfl_down_sync(0xffffffffu, s, off);
    if (lane == 0) g_csq[k] = (float)s;
}

// ---------------------------------------------------------------------------
// Kernel 3: HMMA GEMM + shortlist argmin (identical to R14/R15 — banked WIN).
// ---------------------------------------------------------------------------
__global__ __launch_bounds__(256, 2)
void argmin_hmma_kernel() {
    extern __shared__ char smem[];
    const uint32_t sb = smem_u32(smem);
    float* csqs = (float*)(smem + SMEM_CSQ);

    const int tid  = threadIdx.x;
    const int lane = tid & 31;
    const int wid  = tid >> 5;
    const int wm0  = (wid & 1) * 64;
    const int wn0  = (wid >> 1) * 32;

    const int rowbase = (blockIdx.x >> 1) * TM;
    const int kbase   = (blockIdx.x & 1) * KHALF;

    const char* Ag0 = (const char*)g_xb + (size_t)rowbase * 2048;
    const char* Bg0 = (const char*)g_cb + (size_t)kbase * 2048;

    #pragma unroll
    for (int i = 0; i < KHALF / 256; i++)
        csqs[tid + i * 256] = g_csq[kbase + tid + i * 256];

    const int arow  = lane & 15, ahalf = lane >> 4;
    const int browl = (lane & 7) + ((lane >> 4) << 3);
    const int bhalf = (lane >> 3) & 1;

    auto load_stage = [&](int s, int bf) {
        if (s < NCHT) {
            const int kt = s >> 4, cc = s & 15;
            const uint32_t st = sb + bf * STAGE_BYTES;
            const char* ag = Ag0 + cc * 128;
            const char* bg = Bg0 + (size_t)(kt * TN) * 2048 + cc * 128;
            #pragma unroll
            for (int j = 0; j < 4; j++) {
                const int ch = tid + j * 256;
                const int r = ch >> 3, c = ch & 7;
                CP16(st + r * 128 + ((c ^ (r & 7)) << 4), ag + (size_t)r * 2048 + c * 16);
            }
            const uint32_t bst = st + A_STAGE;
            #pragma unroll
            for (int j = 0; j < 4; j++) {
                const int ch = tid + j * 256;
                const int r = ch >> 3, c = ch & 7;
                CP16(bst + r * 128 + ((c ^ (r & 7)) << 4), bg + (size_t)r * 2048 + c * 16);
            }
        }
        CP_COMMIT();
    };

    load_stage(0, 0); load_stage(1, 1);
    int buf = 0, nbuf = 2;
    __syncthreads();   // csqs visible to all warps

    float runmin[4][2];
    #pragma unroll
    for (int mi = 0; mi < 4; mi++) { runmin[mi][0] = 3.0e38f; runmin[mi][1] = 3.0e38f; }

    for (int kt = 0; kt < NKT; ++kt) {
        float acc[4][4][4];
        #pragma unroll
        for (int mi = 0; mi < 4; mi++)
            #pragma unroll
            for (int ni = 0; ni < 4; ni++)
                #pragma unroll
                for (int q = 0; q < 4; q++) acc[mi][ni][q] = 0.0f;

        for (int cc = 0; cc < NCH; ++cc) {
            const int s = (kt << 4) + cc;
            CP_WAIT1();
            __syncthreads();
            load_stage(s + 2, nbuf);
            const uint32_t st = sb + buf * STAGE_BYTES;
            buf = (buf + 1 == 3) ? 0 : buf + 1;
            nbuf = (nbuf + 1 == 3) ? 0 : nbuf + 1;

            #pragma unroll
            for (int ks = 0; ks < 4; ++ks) {
                uint32_t af[4][4];
                #pragma unroll
                for (int mi = 0; mi < 4; mi++) {
                    const int r = wm0 + mi * 16 + arow;
                    LDSM4(af[mi], st + r * 128 + ((((ks << 1) + ahalf) ^ (r & 7)) << 4));
                }
                uint32_t bfr[2][4];
                #pragma unroll
                for (int p = 0; p < 2; p++) {
                    const int r = wn0 + p * 16 + browl;
                    LDSM4(bfr[p], st + A_STAGE + r * 128 +
                                  ((((ks << 1) + bhalf) ^ (r & 7)) << 4));
                }
                #pragma unroll
                for (int mi = 0; mi < 4; mi++)
                    #pragma unroll
                    for (int ni = 0; ni < 4; ni++)
                        MMA16816(acc[mi][ni], af[mi],
                                 bfr[ni >> 1][(ni & 1) * 2], bfr[ni >> 1][(ni & 1) * 2 + 1]);
            }
        }

        // ---- single-pass epilogue: quad running min + direct append ----
        float csqv[8];
        #pragma unroll
        for (int ni = 0; ni < 4; ni++)
            #pragma unroll
            for (int c = 0; c < 2; c++)
                csqv[ni * 2 + c] =
                    csqs[kt * TN + wn0 + ni * 8 + (lane & 3) * 2 + c];

        #pragma unroll
        for (int mi = 0; mi < 4; mi++)
            #pragma unroll
            for (int rh = 0; rh < 2; rh++) {
                float d[8];
                float dmin = 3.0e38f;
                #pragma unroll
                for (int j = 0; j < 8; j++) {
                    d[j] = fmaf(acc[mi][j >> 1][rh * 2 + (j & 1)], -2.0f, csqv[j]);
                    dmin = fminf(dmin, d[j]);
                }
                dmin = fminf(dmin, __shfl_xor_sync(0xffffffffu, dmin, 1));
                dmin = fminf(dmin, __shfl_xor_sync(0xffffffffu, dmin, 2));
                const float thr = fminf(runmin[mi][rh], dmin) + MARGIN;
                runmin[mi][rh] = fminf(runmin[mi][rh], dmin);
                const int row = rowbase + wm0 + mi * 16 + (lane >> 2) + rh * 8;
                #pragma unroll
                for (int j = 0; j < 8; j++) {
                    if (d[j] < thr) {
                        const int kcol =
                            kbase + kt * TN + wn0 + (j >> 1) * 8 + (lane & 3) * 2 + (j & 1);
                        const int idx = atomicAdd(&g_ccount[row], 1);
                        if (idx < NCAND)
                            g_cand[row][idx] =
                                ((unsigned long long)enc(d[j]) << 32) | (unsigned)kcol;
                    }
                }
            }
    }
}

// ---------------------------------------------------------------------------
// Kernel 4: exact fp32 re-rank (one warp per row) with single-passer fast path.
// ---------------------------------------------------------------------------
__global__ __launch_bounds__(256)
void rerank_kernel(const float* __restrict__ cent) {
    const int lane = threadIdx.x & 31;
    const int row = blockIdx.x * 8 + (threadIdx.x >> 5);
    const int n = g_ccount[row];

    unsigned long long best = ~0ULL;
    if (n <= NCAND) {
        unsigned long long mn = ~0ULL;
        #pragma unroll
        for (int h = 0; h < 4; h++) {
            const int i = lane + h * 32;
            if (i < n) {
                unsigned long long v = g_cand[row][i];
                mn = (v < mn) ? v : mn;
            }
        }
        #pragma unroll
        for (int off = 16; off; off >>= 1) {
            unsigned long long o = __shfl_xor_sync(0xffffffffu, mn, off);
            mn = (o < mn) ? o : mn;
        }
        const unsigned thrk = enc(dec((unsigned)(mn >> 32)) + MARGIN);

        int mycnt = 0;
        #pragma unroll
        for (int h = 0; h < 4; h++) {
            const int i = lane + h * 32;
            if (i < n && (unsigned)(g_cand[row][i] >> 32) < thrk) mycnt++;
        }
        #pragma unroll
        for (int off = 16; off; off >>= 1)
            mycnt += __shfl_xor_sync(0xffffffffu, mycnt, off);

        if (mycnt == 1) {
            if (lane == 0) g_amin[row] = (int)(mn & 0xffffffffu);
            return;
        }

        float4 xv[8];
        const float4* xr = reinterpret_cast<const float4*>(g_xf + (size_t)row * Cc);
        #pragma unroll
        for (int i = 0; i < 8; i++) xv[i] = xr[i * 32 + lane];

        for (int i = 0; i < n; i++) {
            const unsigned long long ki = g_cand[row][i];   // broadcast load
            if ((unsigned)(ki >> 32) >= thrk) continue;
            const int k = (int)(ki & 0xffffffffu);
            const float4* crp = reinterpret_cast<const float4*>(cent + (size_t)k * Cc);
            float s = 0.f;
            #pragma unroll
            for (int i2 = 0; i2 < 8; i2++) {
                float4 cv = crp[i2 * 32 + lane];
                s = fmaf(xv[i2].x, cv.x, s); s = fmaf(xv[i2].y, cv.y, s);
                s = fmaf(xv[i2].z, cv.z, s); s = fmaf(xv[i2].w, cv.w, s);
            }
            #pragma unroll
            for (int off = 16; off; off >>= 1) s += __shfl_xor_sync(0xffffffffu, s, off);
            const float dd = fmaf(s, -2.0f, g_csq[k]);
            unsigned long long key = ((unsigned long long)enc(dd) << 32) | (unsigned)k;
            best = (key < best) ? key : best;
        }
    } else {
        float4 xv[8];
        const float4* xr = reinterpret_cast<const float4*>(g_xf + (size_t)row * Cc);
        #pragma unroll
        for (int i = 0; i < 8; i++) xv[i] = xr[i * 32 + lane];

        for (int k = 0; k < Kk; k++) {
            const float4* crp = reinterpret_cast<const float4*>(cent + (size_t)k * Cc);
            float s = 0.f;
            #pragma unroll
            for (int i2 = 0; i2 < 8; i2++) {
                float4 cv = crp[i2 * 32 + lane];
                s = fmaf(xv[i2].x, cv.x, s); s = fmaf(xv[i2].y, cv.y, s);
                s = fmaf(xv[i2].z, cv.z, s); s = fmaf(xv[i2].w, cv.w, s);
            }
            #pragma unroll
            for (int off = 16; off; off >>= 1) s += __shfl_xor_sync(0xffffffffu, s, off);
            const float dd = fmaf(s, -2.0f, g_csq[k]);
            unsigned long long key = ((unsigned long long)enc(dd) << 32) | (unsigned)k;
            best = (key < best) ? key : best;
        }
    }
    if (lane == 0) g_amin[row] = (int)(best & 0xffffffffu);
}

// ---------------------------------------------------------------------------
// Kernel 5: output = feature - centroid[amin].
// 64x64 tiles, float4 gather (coalesced along c) + float4 feat/out (along t).
// ---------------------------------------------------------------------------
__global__ __launch_bounds__(256)
void output_kernel(const float* __restrict__ feat,
                   const float* __restrict__ cent,
                   float* __restrict__ out) {
    __shared__ float ctile[64][65];
    __shared__ int kidxs[64];
    const int t0 = blockIdx.x * 64, c0 = blockIdx.y * 64, b = blockIdx.z;
    const int tid = threadIdx.x;

    if (tid < 64) kidxs[tid] = g_amin[b * Tt + t0 + tid];
    __syncthreads();

    // gather: 64 t-rows x 64 c values, float4 along c (coalesced)
    #pragma unroll
    for (int i = 0; i < 4; i++) {
        const int idx = tid + i * 256;        // 0..1023
        const int tt = idx >> 4, f4 = idx & 15;
        const float4 v = *reinterpret_cast<const float4*>(
            &cent[(size_t)kidxs[tt] * Cc + c0 + f4 * 4]);
        ctile[tt][f4 * 4 + 0] = v.x; ctile[tt][f4 * 4 + 1] = v.y;
        ctile[tt][f4 * 4 + 2] = v.z; ctile[tt][f4 * 4 + 3] = v.w;
    }
    __syncthreads();

    // out[c][t] = feat[c][t] - ctile[t][c], float4 along t (coalesced)
    #pragma unroll
    for (int i = 0; i < 4; i++) {
        const int idx = tid + i * 256;
        const int cc = idx >> 4, t4 = idx & 15;
        const size_t off =
            (size_t)b * Cc * Tt + (size_t)(c0 + cc) * Tt + t0 + t4 * 4;
        float4 f = *reinterpret_cast<const float4*>(&feat[off]);
        f.x -= ctile[t4 * 4 + 0][cc];
        f.y -= ctile[t4 * 4 + 1][cc];
        f.z -= ctile[t4 * 4 + 2][cc];
        f.w -= ctile[t4 * 4 + 3][cc];
        *reinterpret_cast<float4*>(&out[off]) = f;
    }
}

// ---------------------------------------------------------------------------
extern "C" void kernel_launch(void* const* d_in, const int* in_sizes, int n_in,
                              void* d_out, int out_size) {
    const float* feat = (const float*)d_in[0];
    const float* cent = (const float*)d_in[1];
    float* out = (float*)d_out;

    cudaFuncSetAttribute(argmin_hmma_kernel,
                         cudaFuncAttributeMaxDynamicSharedMemorySize, SMEM_TOTAL);

    convert_kernel<<<dim3(Tt / 64, Cc / 64, Bb), 256>>>(feat);
    csq_kernel<<<Kk / 8, 256>>>(cent);
    argmin_hmma_kernel<<<(Nrows / TM) * 2, 256, SMEM_TOTAL>>>();
    rerank_kernel<<<Nrows / 8, 256>>>(cent);
    output_kernel<<<dim3(Tt / 64, Cc / 64, Bb), 256>>>(feat, cent, out);
}